// round 5
// baseline (speedup 1.0000x reference)
#include <cuda_runtime.h>
#include <cuda_fp16.h>
#include <math.h>

// Problem constants
#define BZ 32
#define TT 256
#define EE 1024
#define HH 1024
#define KK 2048
#define C4 4096
#define NMT 256           // m-tiles (16 cols) per layer
#define NCHUNK 128        // k-chunks of 16
#define BROW 1032         // staged B row stride in halves (2064 B)
#define BMATB 66048       // bytes per staged 32x1024 fp16 matrix
#define ARESB 131072      // L0 resident A slice bytes (4 gates x 64 chunks x 32 lanes x 16B)
#define SMEM_DYN 197120   // max(L0: ARESB+BMATB, L1: 2*BMATB)

// ---------------------------------------------------------------------------
// Device scratch (static; no allocations)
// ---------------------------------------------------------------------------
__device__ __half g_Wt[2][C4][KK];              // transposed weights, fp16
__device__ uint4  g_Wsw[2 * NMT * NCHUNK * 32]; // mma A fragments
__device__ __half g_x[TT * BZ][EE];             // x re-laid [t*32+b][e]
__device__ __half g_hf[2][2][BZ][HH];           // [parity][layer][b][j]
__device__ float  g_h[2][BZ][HH];
__device__ float  g_c[2][BZ][HH];
__device__ float  g_X0[(size_t)TT * C4 * BZ];   // x@W_ih0 + b0, [t][col][b]
__device__ unsigned g_bar;                      // grid barrier counter

// ---------------------------------------------------------------------------
// Helpers
// ---------------------------------------------------------------------------
__device__ __forceinline__ unsigned ldu(const __half* p) {
    return *reinterpret_cast<const unsigned*>(p);
}
__device__ __forceinline__ void mma16816(float d[4], const unsigned* a,
                                         unsigned b0, unsigned b1) {
    asm volatile(
        "mma.sync.aligned.m16n8k16.row.col.f32.f16.f16.f32 "
        "{%0,%1,%2,%3}, {%4,%5,%6,%7}, {%8,%9}, {%0,%1,%2,%3};\n"
        : "+f"(d[0]), "+f"(d[1]), "+f"(d[2]), "+f"(d[3])
        : "r"(a[0]), "r"(a[1]), "r"(a[2]), "r"(a[3]), "r"(b0), "r"(b1));
}
__device__ __forceinline__ void ldm4(unsigned r[4], unsigned addr) {
    asm volatile("ldmatrix.sync.aligned.m8n8.x4.shared.b16 {%0,%1,%2,%3}, [%4];"
                 : "=r"(r[0]), "=r"(r[1]), "=r"(r[2]), "=r"(r[3]) : "r"(addr));
}
__device__ __forceinline__ uint4 lds128(unsigned addr) {
    uint4 v;
    asm volatile("ld.shared.v4.u32 {%0,%1,%2,%3}, [%4];"
                 : "=r"(v.x), "=r"(v.y), "=r"(v.z), "=r"(v.w) : "r"(addr));
    return v;
}
__device__ __forceinline__ float sigf(float x) { return 1.f / (1.f + __expf(-x)); }
__device__ __forceinline__ float tanhfast(float x) {
    float e2 = __expf(-2.f * fabsf(x));
    return copysignf((1.f - e2) / (1.f + e2), x);
}

// ---------------------------------------------------------------------------
// Prep kernels
// ---------------------------------------------------------------------------
__global__ void prep_weights(const float* __restrict__ W_ih0,
                             const float* __restrict__ W_hh0,
                             const float* __restrict__ W_ih1,
                             const float* __restrict__ W_hh1)
{
    __shared__ float tile[32][33];
    int k0 = blockIdx.x * 32;
    int c0 = blockIdx.y * 32;
    int L  = blockIdx.z;
    int tx = threadIdx.x, ty = threadIdx.y;
#pragma unroll
    for (int i = 0; i < 4; i++) {
        int k = k0 + ty + i * 8;
        const float* S; int kr;
        if (L == 0) { if (k < HH) { S = W_hh0; kr = k; } else { S = W_ih0; kr = k - HH; } }
        else        { if (k < HH) { S = W_ih1; kr = k; } else { S = W_hh1; kr = k - HH; } }
        tile[ty + i * 8][tx] = S[(size_t)kr * C4 + c0 + tx];
    }
    __syncthreads();
#pragma unroll
    for (int i = 0; i < 4; i++) {
        int c = c0 + ty + i * 8;
        g_Wt[L][c][k0 + tx] = __float2half(tile[tx][ty + i * 8]);
    }
}

__global__ void swizzle_weights()
{
    const int idx  = blockIdx.x * blockDim.x + threadIdx.x;
    const int lane = idx & 31;
    const int c    = (idx >> 5)  & (NCHUNK - 1);
    const int mt   = (idx >> 12) & (NMT - 1);
    const int L    = (idx >> 20) & 1;
    const int r  = lane >> 2;
    const int ka = (lane & 3) * 2;
    const int col0 = mt * 16 + r;
    const int col1 = col0 + 8;
    const int k0 = c * 16 + ka;
    uint4 f;
    f.x = ldu(&g_Wt[L][col0][k0]);
    f.y = ldu(&g_Wt[L][col1][k0]);
    f.z = ldu(&g_Wt[L][col0][k0 + 8]);
    f.w = ldu(&g_Wt[L][col1][k0 + 8]);
    g_Wsw[idx] = f;
}

__global__ void prep_x(const float* __restrict__ x)
{
    const int N = BZ * TT * EE;
    for (int idx = blockIdx.x * blockDim.x + threadIdx.x; idx < N;
         idx += gridDim.x * blockDim.x) {
        int e  = idx & (EE - 1);
        int bt = idx >> 10;
        int t  = bt & (TT - 1);
        int b  = bt >> 8;
        g_x[t * BZ + b][e] = __float2half(x[idx]);
    }
}

__global__ void zero_states()
{
    int idx = blockIdx.x * blockDim.x + threadIdx.x;
    if (idx == 0) g_bar = 0u;
    const int nhf = 2 * 2 * BZ * HH;
    if (idx < nhf) (&g_hf[0][0][0][0])[idx] = __float2half(0.f);
    const int nf = 2 * BZ * HH;
    if (idx < nf) {
        (&g_h[0][0][0])[idx] = 0.f;
        (&g_c[0][0][0])[idx] = 0.f;
    }
}

__global__ void copy_mask(const float* __restrict__ m, float* __restrict__ dst)
{
    int i = blockIdx.x * blockDim.x + threadIdx.x;
    if (i < BZ * TT) dst[i] = m[i];
}

// ---------------------------------------------------------------------------
// X0 precompute: X0[t][col][b] = sum_e x[t,b,e]*W_ih0[e,col] + b0[col]
// ---------------------------------------------------------------------------
__global__ void __launch_bounds__(256) x0_gemm(const float* __restrict__ b0)
{
    extern __shared__ __align__(16) unsigned char sm[];
    const unsigned smbase = (unsigned)__cvta_generic_to_shared(sm);
    const int gX  = blockIdx.x;
    const int ty  = blockIdx.y;
    const int tid = threadIdx.x, lane = tid & 31, warp = tid >> 5;
    const int w = warp & 3, nh = warp >> 2;
    const int mt = w * 64 + gX;

    const uint4* __restrict__ A = g_Wsw + ((size_t)mt * NCHUNK + 64) * 32 + lane;

    const int ltile = lane >> 3, lrow = lane & 7;
    const int nbb = (ltile >> 1) * 8 + lrow;
    const int kb  = (ltile & 1) * 8;
    const unsigned ldmb = smbase + (((nh * 16 + nbb) * BROW + kb) << 1);

    const int colr = mt * 16 + (lane >> 2);
    const float bia0 = b0[colr];
    const float bia8 = b0[colr + 8];

    for (int tt = 0; tt < 8; tt++) {
        const int t = ty * 8 + tt;
#pragma unroll
        for (int q = 0; q < 16; q++) {
            int idx = tid + q * 256;
            int row = idx >> 7, kc = idx & 127;
            const __half* src = &g_x[t * BZ + row][kc * 8];
            unsigned dst = smbase + row * 2064 + kc * 16;
            asm volatile("cp.async.ca.shared.global [%0], [%1], 16;\n"
                         :: "r"(dst), "l"(src));
        }
        asm volatile("cp.async.commit_group;\ncp.async.wait_group 0;\n");
        __syncthreads();

        float acc0[4] = {0, 0, 0, 0}, acc1[4] = {0, 0, 0, 0};
        uint4 Ac[4], An[4];
#pragma unroll
        for (int cc = 0; cc < 4; cc++) Ac[cc] = A[cc * 32];
        for (int ct = 0; ct < 16; ct++) {
            if (ct < 15) {
#pragma unroll
                for (int cc = 0; cc < 4; cc++) An[cc] = A[((ct + 1) * 4 + cc) * 32];
            }
#pragma unroll
            for (int cc = 0; cc < 4; cc++) {
                const int c = ct * 4 + cc;
                unsigned bb[4];
                ldm4(bb, ldmb + c * 32);
                const unsigned* ap = reinterpret_cast<const unsigned*>(&Ac[cc]);
                mma16816(acc0, ap, bb[0], bb[1]);
                mma16816(acc1, ap, bb[2], bb[3]);
            }
#pragma unroll
            for (int cc = 0; cc < 4; cc++) Ac[cc] = An[cc];
        }
        __syncthreads();

        const size_t base = (size_t)t * C4 * BZ;
        const int bc0 = nh * 16 + (lane & 3) * 2;
        g_X0[base + (size_t)colr * 32 + bc0]           = acc0[0] + bia0;
        g_X0[base + (size_t)colr * 32 + bc0 + 1]       = acc0[1] + bia0;
        g_X0[base + (size_t)(colr + 8) * 32 + bc0]     = acc0[2] + bia8;
        g_X0[base + (size_t)(colr + 8) * 32 + bc0 + 1] = acc0[3] + bia8;
        const int bc1 = bc0 + 8;
        g_X0[base + (size_t)colr * 32 + bc1]           = acc1[0] + bia0;
        g_X0[base + (size_t)colr * 32 + bc1 + 1]       = acc1[1] + bia0;
        g_X0[base + (size_t)(colr + 8) * 32 + bc1]     = acc1[2] + bia8;
        g_X0[base + (size_t)(colr + 8) * 32 + bc1 + 1] = acc1[3] + bia8;
    }
}

// ---------------------------------------------------------------------------
// Persistent kernel: all 256 timesteps, grid barrier between steps.
// 128 blocks x 256 threads, 1 block/SM (co-resident).
//   bx <  64: layer0, 64 cols, K=1024, A resident in SMEM (loaded once)
//   bx >= 64: layer1, 64 cols, K=2048, A streamed from L2
// All h staging uses cp.async.cg (L1 bypass — L1 is stale across steps).
// ---------------------------------------------------------------------------
__global__ void __launch_bounds__(256) lstm_all(
    const float* __restrict__ mask,
    const float* __restrict__ bias1,
    float* __restrict__ out)
{
    extern __shared__ __align__(16) unsigned char sm[];
    const unsigned smbase = (unsigned)__cvta_generic_to_shared(sm);

    const int bx   = blockIdx.x;
    const int L    = bx >> 6;
    const int g    = bx & 63;
    const int tid  = threadIdx.x;
    const int lane = tid & 31;
    const int warp = tid >> 5;
    const int w    = warp & 3;
    const int hf   = warp >> 2;

    // SMEM layout:  L0: [A_res 128K][B 66K(+preS alias)]   L1: [B0 66K][B1 66K] preS alias at 0
    const unsigned boff  = L ? 0u : (unsigned)ARESB;       // B staging base
    float* preS = reinterpret_cast<float*>(sm + boff);

    // ---- L0: load resident A slice once (8192 uint4) ----
    if (L == 0) {
#pragma unroll
        for (int q = 0; q < 32; q++) {
            int idx = tid + q * 256;                 // [0, 8192)
            int ww  = idx >> 11;
            int rest = idx & 2047;                   // chunk*32 + lane
            const uint4* src = g_Wsw + ((size_t)(ww * 64 + g) * NCHUNK) * 32 + rest;
            unsigned dst = smbase + idx * 16;
            asm volatile("cp.async.cg.shared.global [%0], [%1], 16;\n"
                         :: "r"(dst), "l"(src));
        }
        asm volatile("cp.async.commit_group;\ncp.async.wait_group 0;\n");
    }
    __syncthreads();

    // constants for mma addressing
    const int mt    = w * 64 + g;
    const int cbase = L ? hf * 64 : hf * 32;
    const int niter = L ? 16 : 8;
    const uint4* __restrict__ Ag =
        g_Wsw + (((size_t)NMT + mt) * NCHUNK + cbase) * 32 + lane;   // L1 global A
    const unsigned As = smbase + ((unsigned)(w * 2048 + cbase * 32 + lane) << 4); // L0 smem A

    const int ltile = lane >> 3, lrow = lane & 7;
    const int nbb = (ltile >> 1) * 8 + lrow;
    const int kb  = (ltile & 1) * 8;
    const unsigned matoff = L ? hf * BMATB : hf * 1024;
    unsigned ldmb[2];
#pragma unroll
    for (int ng = 0; ng < 2; ng++)
        ldmb[ng] = smbase + boff + matoff + (((ng * 16 + nbb) * BROW + kb) << 1);

    for (int t = 0; t < TT; t++) {
        const int p = t & 1;

        // ---- stage B (h matrices), L1-bypassing ----
        const __half* __restrict__ h0 = &g_hf[p][0][0][0];
        const __half* __restrict__ h1 = &g_hf[p][1][0][0];
        if (L == 0) {
#pragma unroll
            for (int q = 0; q < 16; q++) {
                int idx = tid + q * 256;
                int row = idx >> 7, kc = idx & 127;
                const __half* src = h0 + row * HH + kc * 8;
                unsigned dst = smbase + boff + row * 2064 + kc * 16;
                asm volatile("cp.async.cg.shared.global [%0], [%1], 16;\n"
                             :: "r"(dst), "l"(src));
            }
        } else {
#pragma unroll
            for (int q = 0; q < 32; q++) {
                int idx = tid + q * 256;
                int mat = idx >> 12;
                int row = (idx >> 7) & 31, kc = idx & 127;
                const __half* src = (mat ? h1 : h0) + row * HH + kc * 8;
                unsigned dst = smbase + boff + mat * BMATB + row * 2064 + kc * 16;
                asm volatile("cp.async.cg.shared.global [%0], [%1], 16;\n"
                             :: "r"(dst), "l"(src));
            }
        }
        asm volatile("cp.async.commit_group;\ncp.async.wait_group 0;\n");
        __syncthreads();

        // ---- mma ----
        float acc[4][4];
#pragma unroll
        for (int j = 0; j < 4; j++)
#pragma unroll
            for (int q = 0; q < 4; q++) acc[j][q] = 0.f;

        uint4 Ac[4], An[4];
        if (L == 0) {
#pragma unroll
            for (int cc = 0; cc < 4; cc++) Ac[cc] = lds128(As + cc * 512);
            for (int ct = 0; ct < 8; ct++) {
                if (ct < 7) {
#pragma unroll
                    for (int cc = 0; cc < 4; cc++)
                        An[cc] = lds128(As + (((ct + 1) * 4 + cc) << 9));
                }
#pragma unroll
                for (int cc = 0; cc < 4; cc++) {
                    const int c = ct * 4 + cc;
                    unsigned b01[4], b23[4];
                    ldm4(b01, ldmb[0] + c * 32);
                    ldm4(b23, ldmb[1] + c * 32);
                    const unsigned* ap = reinterpret_cast<const unsigned*>(&Ac[cc]);
                    mma16816(acc[0], ap, b01[0], b01[1]);
                    mma16816(acc[1], ap, b01[2], b01[3]);
                    mma16816(acc[2], ap, b23[0], b23[1]);
                    mma16816(acc[3], ap, b23[2], b23[3]);
                }
#pragma unroll
                for (int cc = 0; cc < 4; cc++) Ac[cc] = An[cc];
            }
        } else {
#pragma unroll
            for (int cc = 0; cc < 4; cc++) Ac[cc] = Ag[cc * 32];
            for (int ct = 0; ct < 16; ct++) {
                if (ct < 15) {
#pragma unroll
                    for (int cc = 0; cc < 4; cc++) An[cc] = Ag[((ct + 1) * 4 + cc) * 32];
                }
#pragma unroll
                for (int cc = 0; cc < 4; cc++) {
                    const int c = ct * 4 + cc;
                    unsigned b01[4], b23[4];
                    ldm4(b01, ldmb[0] + c * 32);
                    ldm4(b23, ldmb[1] + c * 32);
                    const unsigned* ap = reinterpret_cast<const unsigned*>(&Ac[cc]);
                    mma16816(acc[0], ap, b01[0], b01[1]);
                    mma16816(acc[1], ap, b01[2], b01[3]);
                    mma16816(acc[2], ap, b23[0], b23[1]);
                    mma16816(acc[3], ap, b23[2], b23[3]);
                }
#pragma unroll
                for (int cc = 0; cc < 4; cc++) Ac[cc] = An[cc];
            }
        }
        __syncthreads();   // B reads done before preS aliases over it

        // ---- reduce partials via SMEM ----
        {
            const int r = lane >> 2;
            const int q = (lane & 3) * 2;
            float* pS = preS + hf * (64 * 33);
#pragma unroll
            for (int j = 0; j < 4; j++) {
                const int n = j * 8 + q;
                pS[(w * 16 + r) * 33 + n]         = acc[j][0];
                pS[(w * 16 + r) * 33 + n + 1]     = acc[j][1];
                pS[(w * 16 + r + 8) * 33 + n]     = acc[j][2];
                pS[(w * 16 + r + 8) * 33 + n + 1] = acc[j][3];
            }
        }
        __syncthreads();

        // ---- fused pointwise LSTM update ----
#pragma unroll
        for (int e = tid; e < 512; e += 256) {
            const int b  = e >> 4;
            const int ul = e & 15;
            const int j  = g * 16 + ul;
            float f  = preS[ul * 33 + b]        + preS[64 * 33 + ul * 33 + b];
            float i  = preS[(16 + ul) * 33 + b] + preS[64 * 33 + (16 + ul) * 33 + b];
            float o  = preS[(32 + ul) * 33 + b] + preS[64 * 33 + (32 + ul) * 33 + b];
            float gg = preS[(48 + ul) * 33 + b] + preS[64 * 33 + (48 + ul) * 33 + b];
            if (L == 0) {
                const size_t xb = (size_t)t * C4 * BZ + b;
                f  += g_X0[xb + (size_t)j * 32];
                i  += g_X0[xb + (size_t)(HH + j) * 32];
                o  += g_X0[xb + (size_t)(2 * HH + j) * 32];
                gg += g_X0[xb + (size_t)(3 * HH + j) * 32];
            } else {
                f  += bias1[j];
                i  += bias1[HH + j];
                o  += bias1[2 * HH + j];
                gg += bias1[3 * HH + j];
            }
            const float m  = mask[b * TT + t];
            const float cp = g_c[L][b][j];
            const float hp = g_h[L][b][j];

            float cn = sigf(f) * cp + sigf(i) * tanhfast(gg);
            cn = cn * m + cp * (1.f - m);
            float hn = sigf(o) * tanhfast(cn);
            hn = hn * m + hp * (1.f - m);

            g_c[L][b][j] = cn;
            g_h[L][b][j] = hn;
            g_hf[p ^ 1][L][b][j] = __float2half(hn);
            if (L) out[((size_t)b * TT + t) * HH + j] = hn;
        }

        // ---- grid barrier (skip after last step) ----
        if (t < TT - 1) {
            __syncthreads();
            if (tid == 0) {
                __threadfence();
                atomicAdd(&g_bar, 1u);
                const unsigned target = 128u * (unsigned)(t + 1);
                unsigned v;
                do {
                    asm volatile("ld.acquire.gpu.global.u32 %0, [%1];"
                                 : "=r"(v) : "l"(&g_bar));
                } while (v < target);
            }
            __syncthreads();
        }
    }
}

// ---------------------------------------------------------------------------
extern "C" void kernel_launch(void* const* d_in, const int* in_sizes, int n_in,
                              void* d_out, int out_size)
{
    const float* x     = (const float*)d_in[0];
    const float* mask  = (const float*)d_in[1];
    const float* W_ih0 = (const float*)d_in[2];
    const float* W_hh0 = (const float*)d_in[3];
    const float* bs0   = (const float*)d_in[4];
    const float* W_ih1 = (const float*)d_in[5];
    const float* W_hh1 = (const float*)d_in[6];
    const float* bs1   = (const float*)d_in[7];
    float* out = (float*)d_out;

    static bool attr_done = false;
    if (!attr_done) {
        cudaFuncSetAttribute(x0_gemm, cudaFuncAttributeMaxDynamicSharedMemorySize, BMATB);
        cudaFuncSetAttribute(lstm_all, cudaFuncAttributeMaxDynamicSharedMemorySize, SMEM_DYN);
        attr_done = true;
    }

    prep_weights<<<dim3(KK / 32, C4 / 32, 2), dim3(32, 8)>>>(W_ih0, W_hh0, W_ih1, W_hh1);
    swizzle_weights<<<(2 * NMT * NCHUNK * 32) / 256, 256>>>();
    prep_x<<<1024, 256>>>(x);
    zero_states<<<512, 256>>>();
    x0_gemm<<<dim3(64, 32), 256, BMATB>>>(bs0);

    lstm_all<<<128, 256, SMEM_DYN>>>(mask, bs1, out);

    if (out_size >= BZ * TT * HH + BZ * TT) {
        copy_mask<<<(BZ * TT + 255) / 256, 256>>>(mask, out + (size_t)BZ * TT * HH);
    }
}